// round 7
// baseline (speedup 1.0000x reference)
#include <cuda_runtime.h>
#include <cuda.h>
#include <cstdint>

// ============================================================================
// GraphConvolution: out = adj[16384,16384] @ (x[16384,64] @ W[64,64]) + bias
//
// Round 7: round-3 topology (8 compute warps = 4 row groups x 2 kgroups,
// TILE_K=32, STAGES=8) + software-pipelined consumer:
//   - fragments double-buffered in registers
//   - smem stage released (empty-arrive) right after frag load, BEFORE mma
//   - next iteration's loads overlap current iteration's 64 HMMAs
// __syncwarp before the lid0 release-arrive orders all lanes' LDS.
// ============================================================================

#define N_ROWS 16384
#define K_DIM  16384
#define IN_F   64
#define OUT_F  64

#define TILE_M 128
#define TILE_K 32                       // 32 fp32 = 128 B = SW128 atom row
#define STAGES 8
#define N_ITERS (K_DIM / TILE_K)        // 512

#define ADJ_TILE_BYTES (TILE_M * 128)   // 16384
#define B_TILE_BYTES   (OUT_F * 128)    // 8192
#define STAGE_BYTES    (ADJ_TILE_BYTES + B_TILE_BYTES)  // 24576

#define OFF_BARS  0                     // per stage: full @ 16*s, empty @ 16*s+8
#define OFF_TILES 1024
#define SMEM_BYTES (OFF_TILES + STAGES * STAGE_BYTES)   // 197632

#define N_CWARPS 8
#define PART_STRIDE 66                  // padded row stride (floats)

// ---------------------------------------------------------------- PTX helpers
__device__ __forceinline__ uint32_t smem_to_u32(const void* p) {
    uint32_t a;
    asm("{ .reg .u64 t; cvta.to.shared.u64 t, %1; cvt.u32.u64 %0, t; }" : "=r"(a) : "l"(p));
    return a;
}

#define MBARRIER_INIT(addr, count) \
    asm volatile("mbarrier.init.shared.b64 [%0], %1;" :: "r"((uint32_t)(addr)), "r"((uint32_t)(count)) : "memory")

#define MBARRIER_ARRIVE(addr) \
    asm volatile("mbarrier.arrive.release.cta.shared::cta.b64 _, [%0];" :: "r"((uint32_t)(addr)) : "memory")

#define MBARRIER_EXPECT_TX(addr, bytes) \
    asm volatile("mbarrier.arrive.expect_tx.shared.b64 _, [%0], %1;" :: "r"((uint32_t)(addr)), "r"((uint32_t)(bytes)) : "memory")

#define MBARRIER_WAIT_PARITY(addr, parity) do {                                      \
    uint32_t _mbar = (uint32_t)(addr);                                               \
    uint32_t _par  = (uint32_t)(parity);                                             \
    uint32_t _done;                                                                  \
    asm volatile(                                                                    \
        "{\n\t.reg .pred p;\n\t"                                                     \
        "mbarrier.try_wait.parity.acquire.cta.shared::cta.b64 p, [%1], %2;\n\t"      \
        "selp.b32 %0, 1, 0, p;\n\t}"                                                 \
        : "=r"(_done) : "r"(_mbar), "r"(_par) : "memory");                           \
    if (!_done) {                                                                    \
        asm volatile(                                                                \
            "{\n\t.reg .pred P1;\n\t"                                                \
            "WAIT_LOOP_%=:\n\t"                                                      \
            "mbarrier.try_wait.parity.acquire.cta.shared::cta.b64 P1, [%0], %1, 0x989680;\n\t" \
            "@P1 bra.uni WAIT_DONE_%=;\n\t"                                          \
            "bra.uni WAIT_LOOP_%=;\n\t"                                              \
            "WAIT_DONE_%=:\n\t}"                                                     \
            :: "r"(_mbar), "r"(_par) : "memory");                                    \
    }                                                                                \
} while (0)

__device__ __forceinline__ void tma_load_2d_g(uint32_t smem_addr, const CUtensorMap* map,
                                              int cx, int cy, uint32_t mbar) {
    asm volatile(
        "cp.async.bulk.tensor.2d.shared::cta.global.tile.mbarrier::complete_tx::bytes "
        "[%0], [%1, {%2, %3}], [%4];"
        :: "r"(smem_addr), "l"(map), "r"(cx), "r"(cy), "r"(mbar) : "memory");
}

__device__ __forceinline__ uint32_t lds32(uint32_t a) {
    uint32_t v;
    asm volatile("ld.shared.b32 %0, [%1];" : "=r"(v) : "r"(a));
    return v;
}

__device__ __forceinline__ uint32_t f2tf32(uint32_t bits) {
    uint32_t o;
    asm("cvt.rna.tf32.f32 %0, %1;" : "=r"(o) : "f"(__uint_as_float(bits)));
    return o;
}

__device__ __forceinline__ void mma_tf32(float* c,
                                         uint32_t a0, uint32_t a1, uint32_t a2, uint32_t a3,
                                         uint32_t b0, uint32_t b1) {
    asm volatile(
        "mma.sync.aligned.m16n8k8.row.col.f32.tf32.tf32.f32 "
        "{%0,%1,%2,%3}, {%4,%5,%6,%7}, {%8,%9}, {%0,%1,%2,%3};"
        : "+f"(c[0]), "+f"(c[1]), "+f"(c[2]), "+f"(c[3])
        : "r"(a0), "r"(a1), "r"(a2), "r"(a3), "r"(b0), "r"(b1));
}

// ---------------------------------------------------------------- scratch
__device__ __align__(1024) float g_supT[(size_t)OUT_F * K_DIM];  // 4 MiB

// ---------------------------------------------------------------- kernel 1
__global__ void __launch_bounds__(256) gcn_support_kernel(const float* __restrict__ x,
                                                          const float* __restrict__ w,
                                                          float* __restrict__ supT) {
    __shared__ float ws[IN_F * OUT_F];
    int tid = threadIdx.x;
    for (int i = tid; i < IN_F * OUT_F; i += 256) ws[i] = w[i];
    __syncthreads();

    int k  = blockIdx.x * 64 + (tid & 63);
    int n0 = (tid >> 6) * (OUT_F / 4);

    float xr[IN_F];
    const float4* xv = reinterpret_cast<const float4*>(x + (size_t)k * IN_F);
#pragma unroll
    for (int i = 0; i < IN_F / 4; i++) {
        float4 v = xv[i];
        xr[4 * i] = v.x; xr[4 * i + 1] = v.y; xr[4 * i + 2] = v.z; xr[4 * i + 3] = v.w;
    }
#pragma unroll 4
    for (int nn = 0; nn < OUT_F / 4; nn++) {
        int n = n0 + nn;
        float acc = 0.f;
#pragma unroll
        for (int i = 0; i < IN_F; i++) acc = fmaf(xr[i], ws[i * OUT_F + n], acc);
        uint32_t t;
        asm("cvt.rna.tf32.f32 %0, %1;" : "=r"(t) : "f"(acc));  // pre-round to tf32
        supT[(size_t)n * K_DIM + k] = __uint_as_float(t);
    }
}

// ---------------------------------------------------------------- kernel 2
// 9 warps: wid 0..7 compute (4 row groups x 2 kgroups), wid 8 = producer.

// Load this warp's fragments for the stage at smem offset, A rna-rounded.
#define LOAD_FRAGS(AF, BF) do {                                                 \
    uint32_t st_ = sb + OFF_TILES + (uint32_t)s * STAGE_BYTES;                  \
    uint32_t sB_ = st_ + ADJ_TILE_BYTES;                                        \
    _Pragma("unroll")                                                           \
    for (int ks = 0; ks < 2; ks++) {                                            \
        uint32_t c0 = cb0s[ks], c1 = cb1s[ks];                                  \
        (AF)[ks][0] = f2tf32(lds32(st_ + rA0 + c0));                            \
        (AF)[ks][1] = f2tf32(lds32(st_ + rA0 + 1024 + c0));                     \
        (AF)[ks][2] = f2tf32(lds32(st_ + rA0 + c1));                            \
        (AF)[ks][3] = f2tf32(lds32(st_ + rA0 + 1024 + c1));                     \
        (AF)[ks][4] = f2tf32(lds32(st_ + rA0 + 2048 + c0));                     \
        (AF)[ks][5] = f2tf32(lds32(st_ + rA0 + 3072 + c0));                     \
        (AF)[ks][6] = f2tf32(lds32(st_ + rA0 + 2048 + c1));                     \
        (AF)[ks][7] = f2tf32(lds32(st_ + rA0 + 3072 + c1));                     \
        _Pragma("unroll")                                                       \
        for (int nt = 0; nt < 8; nt++) {                                        \
            (BF)[ks][2 * nt]     = lds32(sB_ + rB[nt] + c0);                    \
            (BF)[ks][2 * nt + 1] = lds32(sB_ + rB[nt] + c1);                    \
        }                                                                       \
    }                                                                           \
} while (0)

// wait full(s), load frags, release stage (syncwarp orders all lanes' LDS),
// advance stage/phase.
#define PIPE_LOAD(AF, BF) do {                                                  \
    uint32_t fb_ = sb + OFF_BARS + (uint32_t)s * 16;                            \
    MBARRIER_WAIT_PARITY(fb_, ph);                                              \
    LOAD_FRAGS(AF, BF);                                                         \
    __syncwarp();                                                               \
    if (lid == 0) MBARRIER_ARRIVE(fb_ + 8);                                     \
    if (++s == STAGES) { s = 0; ph ^= 1; }                                      \
} while (0)

#define DO_MMA(AF, BF) do {                                                     \
    _Pragma("unroll")                                                           \
    for (int ks = 0; ks < 2; ks++) {                                            \
        _Pragma("unroll")                                                       \
        for (int nt = 0; nt < 8; nt++) {                                        \
            mma_tf32(acc[0][nt], (AF)[ks][0], (AF)[ks][1], (AF)[ks][2],         \
                     (AF)[ks][3], (BF)[ks][2 * nt], (BF)[ks][2 * nt + 1]);      \
            mma_tf32(acc[1][nt], (AF)[ks][4], (AF)[ks][5], (AF)[ks][6],         \
                     (AF)[ks][7], (BF)[ks][2 * nt], (BF)[ks][2 * nt + 1]);      \
        }                                                                       \
    }                                                                           \
} while (0)

__global__ void __launch_bounds__(288, 1) gcn_gemm_kernel(
    const __grid_constant__ CUtensorMap madj,
    const __grid_constant__ CUtensorMap msup,
    float* __restrict__ out,
    const float* __restrict__ bias)
{
    extern __shared__ char smem[];
    uint32_t sb = smem_to_u32(smem);
    int tid = threadIdx.x;
    int wid = tid >> 5;
    int lid = tid & 31;
    int m0 = blockIdx.x * TILE_M;

    if (tid == 0) {
        for (int s = 0; s < STAGES; s++) {
            MBARRIER_INIT(sb + OFF_BARS + s * 16, 1);            // full: 1 expect_tx
            MBARRIER_INIT(sb + OFF_BARS + s * 16 + 8, N_CWARPS); // empty: 8 arrives
        }
    }
    __syncthreads();

    if (wid == 8) {
        if (lid == 0) {
            // -------- producer: TMA loads, backpressured by empty barriers
            int s = 0; uint32_t ph = 1;  // flipped phase: first STAGES waits pass
            for (int it = 0; it < N_ITERS; it++) {
                uint32_t fb = sb + OFF_BARS + s * 16;
                MBARRIER_WAIT_PARITY(fb + 8, ph);
                MBARRIER_EXPECT_TX(fb, STAGE_BYTES);
                uint32_t a_sm = sb + OFF_TILES + s * STAGE_BYTES;
                tma_load_2d_g(a_sm,                  &madj, it * TILE_K, m0, fb);
                tma_load_2d_g(a_sm + ADJ_TILE_BYTES, &msup, it * TILE_K, 0,  fb);
                if (++s == STAGES) { s = 0; ph ^= 1; }
            }
        }
        return;
    }

    // -------- compute warps
    int cwid   = wid & 3;      // row group: rows [32*cwid, 32*cwid+32)
    int kgroup = wid >> 2;     // 0 -> ks {0,1}, 1 -> ks {2,3}
    int g = lid >> 2;          // 0..7
    int t = lid & 3;           // 0..3
    uint32_t xorv = (uint32_t)g << 4;   // SW128 swizzle term (rows used == g mod 8)

    uint32_t rA0 = (uint32_t)(cwid * 32 + g) * 128;   // mt0 upper 8 rows
    uint32_t rB[8];
#pragma unroll
    for (int nt = 0; nt < 8; nt++) rB[nt] = (uint32_t)(nt * 8 + g) * 128;

    uint32_t cb0s[2], cb1s[2];
#pragma unroll
    for (int ks = 0; ks < 2; ks++) {
        cb0s[ks] = ((uint32_t)(kgroup * 64 + ks * 32 + t * 4)) ^ xorv;
        cb1s[ks] = ((uint32_t)(kgroup * 64 + ks * 32 + t * 4 + 16)) ^ xorv;
    }

    float acc[2][8][4];
#pragma unroll
    for (int mt = 0; mt < 2; mt++)
#pragma unroll
        for (int nt = 0; nt < 8; nt++)
#pragma unroll
            for (int c = 0; c < 4; c++) acc[mt][nt][c] = 0.f;

    uint32_t aF0[2][8], bF0[2][16], aF1[2][8], bF1[2][16];

    int s = 0; uint32_t ph = 0;

    // -------- software-pipelined mainloop
    PIPE_LOAD(aF0, bF0);                        // it = 0
#pragma unroll 1
    for (int it = 0; it < N_ITERS - 2; it += 2) {
        PIPE_LOAD(aF1, bF1);                    // it+1
        DO_MMA(aF0, bF0);                       // it
        PIPE_LOAD(aF0, bF0);                    // it+2
        DO_MMA(aF1, bF1);                       // it+1
    }
    PIPE_LOAD(aF1, bF1);                        // it = N_ITERS-1
    DO_MMA(aF0, bF0);                           // N_ITERS-2
    DO_MMA(aF1, bF1);                           // N_ITERS-1

    // -------- drain barrier: all compute warps done with tile smem; the
    // producer's last TMA completed (its full barrier was consumed above).
    asm volatile("bar.sync 1, 256;" ::: "memory");

    // -------- reduction: kgroup 1 writes partials to smem, kgroup 0 adds
    float* part = reinterpret_cast<float*>(smem + OFF_TILES);
    if (kgroup == 1) {
#pragma unroll
        for (int mt = 0; mt < 2; mt++) {
            int r0 = cwid * 32 + mt * 16 + g;
#pragma unroll
            for (int nt = 0; nt < 8; nt++) {
                int col = nt * 8 + 2 * t;
                *reinterpret_cast<float2*>(part + (size_t)r0 * PART_STRIDE + col) =
                    make_float2(acc[0 + (mt)][nt][0], acc[mt][nt][1]);
                *reinterpret_cast<float2*>(part + (size_t)(r0 + 8) * PART_STRIDE + col) =
                    make_float2(acc[mt][nt][2], acc[mt][nt][3]);
            }
        }
    }
    asm volatile("bar.sync 1, 256;" ::: "memory");

    if (kgroup == 0) {
        const float2* b2 = reinterpret_cast<const float2*>(bias);
        int row0 = m0 + cwid * 32 + g;
#pragma unroll
        for (int mt = 0; mt < 2; mt++) {
            int rloc = cwid * 32 + mt * 16 + g;
            int r = row0 + mt * 16;
#pragma unroll
            for (int nt = 0; nt < 8; nt++) {
                int col = nt * 8 + 2 * t;
                float2 bv = b2[col >> 1];
                float2 p0 = *reinterpret_cast<const float2*>(part + (size_t)rloc * PART_STRIDE + col);
                float2 p1 = *reinterpret_cast<const float2*>(part + (size_t)(rloc + 8) * PART_STRIDE + col);
                *reinterpret_cast<float2*>(out + (size_t)r * OUT_F + col) =
                    make_float2(acc[mt][nt][0] + p0.x + bv.x, acc[mt][nt][1] + p0.y + bv.y);
                *reinterpret_cast<float2*>(out + (size_t)(r + 8) * OUT_F + col) =
                    make_float2(acc[mt][nt][2] + p1.x + bv.x, acc[mt][nt][3] + p1.y + bv.y);
            }
        }
    }
}

// ---------------------------------------------------------------- host
typedef CUresult (*tmap_encode_fn)(
    CUtensorMap*, CUtensorMapDataType, cuuint32_t, void*,
    const cuuint64_t*, const cuuint64_t*, const cuuint32_t*, const cuuint32_t*,
    CUtensorMapInterleave, CUtensorMapSwizzle, CUtensorMapL2promotion,
    CUtensorMapFloatOOBfill);

extern "C" void kernel_launch(void* const* d_in, const int* in_sizes, int n_in,
                              void* d_out, int out_size) {
    const float* x    = (const float*)d_in[0];
    const float* adj  = (const float*)d_in[1];
    const float* w    = (const float*)d_in[2];
    const float* bias = (const float*)d_in[3];
    float* out = (float*)d_out;

    void* supT_ptr = nullptr;
    cudaGetSymbolAddress(&supT_ptr, g_supT);
    float* supT = (float*)supT_ptr;

    gcn_support_kernel<<<K_DIM / 64, 256>>>(x, w, supT);

    // Driver entry point via cudart (no -lcuda link dependency)
    tmap_encode_fn enc = nullptr;
    cudaDriverEntryPointQueryResult qr;
    cudaGetDriverEntryPointByVersion("cuTensorMapEncodeTiled", (void**)&enc, 12000,
                                     cudaEnableDefault, &qr);

    CUtensorMap madj{}, msup{};
    {
        cuuint64_t dims[2]    = {(cuuint64_t)K_DIM, (cuuint64_t)N_ROWS};
        cuuint64_t strides[1] = {(cuuint64_t)K_DIM * sizeof(float)};
        cuuint32_t box[2]     = {TILE_K, TILE_M};   // 128B x 128 rows, SW128
        cuuint32_t es[2]      = {1, 1};
        enc(&madj, CU_TENSOR_MAP_DATA_TYPE_FLOAT32, 2, (void*)adj,
            dims, strides, box, es,
            CU_TENSOR_MAP_INTERLEAVE_NONE, CU_TENSOR_MAP_SWIZZLE_128B,
            CU_TENSOR_MAP_L2_PROMOTION_L2_128B, CU_TENSOR_MAP_FLOAT_OOB_FILL_NONE);
    }
    {
        cuuint64_t dims[2]    = {(cuuint64_t)K_DIM, (cuuint64_t)OUT_F};
        cuuint64_t strides[1] = {(cuuint64_t)K_DIM * sizeof(float)};
        cuuint32_t box[2]     = {TILE_K, OUT_F};    // 128B x 64 rows, SW128
        cuuint32_t es[2]      = {1, 1};
        enc(&msup, CU_TENSOR_MAP_DATA_TYPE_FLOAT32, 2, (void*)supT,
            dims, strides, box, es,
            CU_TENSOR_MAP_INTERLEAVE_NONE, CU_TENSOR_MAP_SWIZZLE_128B,
            CU_TENSOR_MAP_L2_PROMOTION_L2_128B, CU_TENSOR_MAP_FLOAT_OOB_FILL_NONE);
    }

    cudaFuncSetAttribute(gcn_gemm_kernel, cudaFuncAttributeMaxDynamicSharedMemorySize,
                         SMEM_BYTES);
    gcn_gemm_kernel<<<N_ROWS / TILE_M, 288, SMEM_BYTES>>>(madj, msup, out, bias);
}

// round 8
// speedup vs baseline: 1.2795x; 1.2795x over previous
#include <cuda_runtime.h>
#include <cuda.h>
#include <cuda_fp16.h>
#include <cstdint>

// ============================================================================
// GraphConvolution: out = adj[16384,16384] @ (x[16384,64] @ W[64,64]) + bias
//
// Round 8: fp16 MMA (m16n8k16) — same rounding error as tf32 rna (2^-11),
// half the MMA instructions, quarter the tensor-pipe cycles.
//  - kernel 1 writes supT as fp16 K-major [64][16384] (B operand, SW128 TMA)
//  - adj stays fp32 (SW128 TMA), converted in-register: LDS.64 + cvt.rn.f16x2
//  - TILE_K=64, STAGES=4, 8 compute warps (4 row x 2 kgroups), in-order loop
//    (round-3 structure: no SW pipelining — falsified in round 7).
// ============================================================================

#define N_ROWS 16384
#define K_DIM  16384
#define IN_F   64
#define OUT_F  64

#define TILE_M 128
#define TILE_K 64
#define STAGES 4
#define N_ITERS (K_DIM / TILE_K)        // 256

#define A_REG_BYTES 16384               // 128 rows x 128B (32 fp32 cols)
#define B_TILE_BYTES 8192               // 64 rows x 128B (64 fp16 cols)
#define OFF_A0 0
#define OFF_A1 16384
#define OFF_B  32768
#define STAGE_BYTES 40960

#define OFF_BARS  0                     // per stage: full @ 16*s, empty @ 16*s+8
#define OFF_TILES 1024
#define SMEM_BYTES (OFF_TILES + STAGES * STAGE_BYTES)   // 164864

#define N_CWARPS 8
#define PART_STRIDE 66                  // padded row stride (floats)

// ---------------------------------------------------------------- PTX helpers
__device__ __forceinline__ uint32_t smem_to_u32(const void* p) {
    uint32_t a;
    asm("{ .reg .u64 t; cvta.to.shared.u64 t, %1; cvt.u32.u64 %0, t; }" : "=r"(a) : "l"(p));
    return a;
}

#define MBARRIER_INIT(addr, count) \
    asm volatile("mbarrier.init.shared.b64 [%0], %1;" :: "r"((uint32_t)(addr)), "r"((uint32_t)(count)) : "memory")

#define MBARRIER_ARRIVE(addr) \
    asm volatile("mbarrier.arrive.shared.b64 _, [%0];" :: "r"((uint32_t)(addr)) : "memory")

#define MBARRIER_EXPECT_TX(addr, bytes) \
    asm volatile("mbarrier.arrive.expect_tx.shared.b64 _, [%0], %1;" :: "r"((uint32_t)(addr)), "r"((uint32_t)(bytes)) : "memory")

#define MBARRIER_WAIT_PARITY(addr, parity) do {                                      \
    uint32_t _mbar = (uint32_t)(addr);                                               \
    uint32_t _par  = (uint32_t)(parity);                                             \
    uint32_t _done;                                                                  \
    asm volatile(                                                                    \
        "{\n\t.reg .pred p;\n\t"                                                     \
        "mbarrier.try_wait.parity.acquire.cta.shared::cta.b64 p, [%1], %2;\n\t"      \
        "selp.b32 %0, 1, 0, p;\n\t}"                                                 \
        : "=r"(_done) : "r"(_mbar), "r"(_par) : "memory");                           \
    if (!_done) {                                                                    \
        asm volatile(                                                                \
            "{\n\t.reg .pred P1;\n\t"                                                \
            "WAIT_LOOP_%=:\n\t"                                                      \
            "mbarrier.try_wait.parity.acquire.cta.shared::cta.b64 P1, [%0], %1, 0x989680;\n\t" \
            "@P1 bra.uni WAIT_DONE_%=;\n\t"                                          \
            "bra.uni WAIT_LOOP_%=;\n\t"                                              \
            "WAIT_DONE_%=:\n\t}"                                                     \
            :: "r"(_mbar), "r"(_par) : "memory");                                    \
    }                                                                                \
} while (0)

__device__ __forceinline__ void tma_load_2d_g(uint32_t smem_addr, const CUtensorMap* map,
                                              int cx, int cy, uint32_t mbar) {
    asm volatile(
        "cp.async.bulk.tensor.2d.shared::cta.global.tile.mbarrier::complete_tx::bytes "
        "[%0], [%1, {%2, %3}], [%4];"
        :: "r"(smem_addr), "l"(map), "r"(cx), "r"(cy), "r"(mbar) : "memory");
}

__device__ __forceinline__ uint32_t lds32(uint32_t a) {
    uint32_t v;
    asm volatile("ld.shared.b32 %0, [%1];" : "=r"(v) : "r"(a));
    return v;
}

__device__ __forceinline__ float2 lds64(uint32_t a) {
    float2 v;
    asm volatile("ld.shared.v2.f32 {%0, %1}, [%2];" : "=f"(v.x), "=f"(v.y) : "r"(a));
    return v;
}

// pack two fp32 -> fp16x2 (lo = second operand)
__device__ __forceinline__ uint32_t packh2(float hi, float lo) {
    uint32_t d;
    asm("cvt.rn.f16x2.f32 %0, %1, %2;" : "=r"(d) : "f"(hi), "f"(lo));
    return d;
}

__device__ __forceinline__ void mma_f16(float* c,
                                        uint32_t a0, uint32_t a1, uint32_t a2, uint32_t a3,
                                        uint32_t b0, uint32_t b1) {
    asm volatile(
        "mma.sync.aligned.m16n8k16.row.col.f32.f16.f16.f32 "
        "{%0,%1,%2,%3}, {%4,%5,%6,%7}, {%8,%9}, {%0,%1,%2,%3};"
        : "+f"(c[0]), "+f"(c[1]), "+f"(c[2]), "+f"(c[3])
        : "r"(a0), "r"(a1), "r"(a2), "r"(a3), "r"(b0), "r"(b1));
}

// ---------------------------------------------------------------- scratch
__device__ __align__(1024) __half g_supT[(size_t)OUT_F * K_DIM];  // 2 MiB

// ---------------------------------------------------------------- kernel 1
__global__ void __launch_bounds__(256) gcn_support_kernel(const float* __restrict__ x,
                                                          const float* __restrict__ w,
                                                          __half* __restrict__ supT) {
    __shared__ float ws[IN_F * OUT_F];
    int tid = threadIdx.x;
    for (int i = tid; i < IN_F * OUT_F; i += 256) ws[i] = w[i];
    __syncthreads();

    int k  = blockIdx.x * 64 + (tid & 63);
    int n0 = (tid >> 6) * (OUT_F / 4);

    float xr[IN_F];
    const float4* xv = reinterpret_cast<const float4*>(x + (size_t)k * IN_F);
#pragma unroll
    for (int i = 0; i < IN_F / 4; i++) {
        float4 v = xv[i];
        xr[4 * i] = v.x; xr[4 * i + 1] = v.y; xr[4 * i + 2] = v.z; xr[4 * i + 3] = v.w;
    }
#pragma unroll 4
    for (int nn = 0; nn < OUT_F / 4; nn++) {
        int n = n0 + nn;
        float acc = 0.f;
#pragma unroll
        for (int i = 0; i < IN_F; i++) acc = fmaf(xr[i], ws[i * OUT_F + n], acc);
        supT[(size_t)n * K_DIM + k] = __float2half_rn(acc);
    }
}

// ---------------------------------------------------------------- kernel 2
// 9 warps: wid 0..7 compute (4 row groups x 2 kgroups), wid 8 = producer.
__global__ void __launch_bounds__(288, 1) gcn_gemm_kernel(
    const __grid_constant__ CUtensorMap madj,
    const __grid_constant__ CUtensorMap msup,
    float* __restrict__ out,
    const float* __restrict__ bias)
{
    extern __shared__ char smem[];
    uint32_t sb = smem_to_u32(smem);
    int tid = threadIdx.x;
    int wid = tid >> 5;
    int lid = tid & 31;
    int m0 = blockIdx.x * TILE_M;

    if (tid == 0) {
        for (int s = 0; s < STAGES; s++) {
            MBARRIER_INIT(sb + OFF_BARS + s * 16, 1);            // full: 1 expect_tx
            MBARRIER_INIT(sb + OFF_BARS + s * 16 + 8, N_CWARPS); // empty: 8 arrives
        }
    }
    __syncthreads();

    if (wid == 8) {
        if (lid == 0) {
            // -------- producer: 3 TMA loads per stage (A k0-31, A k32-63, B k0-63)
            int s = 0; uint32_t ph = 1;  // flipped phase: first STAGES waits pass
            for (int it = 0; it < N_ITERS; it++) {
                uint32_t fb = sb + OFF_BARS + s * 16;
                MBARRIER_WAIT_PARITY(fb + 8, ph);
                MBARRIER_EXPECT_TX(fb, STAGE_BYTES);
                uint32_t st = sb + OFF_TILES + s * STAGE_BYTES;
                int k0 = it * TILE_K;
                tma_load_2d_g(st + OFF_A0, &madj, k0,      m0, fb);
                tma_load_2d_g(st + OFF_A1, &madj, k0 + 32, m0, fb);
                tma_load_2d_g(st + OFF_B,  &msup, k0,      0,  fb);
                if (++s == STAGES) { s = 0; ph ^= 1; }
            }
        }
        return;
    }

    // -------- compute warps
    int cwid   = wid & 3;      // row group: rows [32*cwid, 32*cwid+32)
    int kgroup = wid >> 2;     // owns k32 half: kgroup 0 -> k0-31, 1 -> k32-63
    int g = lid >> 2;          // 0..7
    int t = lid & 3;           // 0..3
    uint32_t xorv = (uint32_t)g << 4;   // SW128 swizzle term (rows used == g mod 8)

    uint32_t rA0 = (uint32_t)(cwid * 32 + g) * 128;   // row (cwid*32+g) byte offset
    uint32_t rB[8];
#pragma unroll
    for (int nt = 0; nt < 8; nt++) rB[nt] = (uint32_t)(nt * 8 + g) * 128;

    // A pair byte-cols per k16 slab ks2: k=2t -> 8t, k=2t+8 -> 8t+32
    uint32_t cA0[2], cA1[2];
    // B byte-cols: global k16 slab = kgroup*2+ks2; b0 at 4t, b1 at 4t+16
    uint32_t cB0[2], cB1[2];
#pragma unroll
    for (int ks2 = 0; ks2 < 2; ks2++) {
        cA0[ks2] = ((uint32_t)(ks2 * 64 + 8 * t))      ^ xorv;
        cA1[ks2] = ((uint32_t)(ks2 * 64 + 8 * t + 32)) ^ xorv;
        uint32_t kk = (uint32_t)(kgroup * 2 + ks2);
        cB0[ks2] = (kk * 32 + 4 * t)      ^ xorv;
        cB1[ks2] = (kk * 32 + 4 * t + 16) ^ xorv;
    }

    float acc[2][8][4];
#pragma unroll
    for (int mt = 0; mt < 2; mt++)
#pragma unroll
        for (int nt = 0; nt < 8; nt++)
#pragma unroll
            for (int c = 0; c < 4; c++) acc[mt][nt][c] = 0.f;

    int s = 0; uint32_t ph = 0;
    for (int it = 0; it < N_ITERS; it++) {
        uint32_t fb = sb + OFF_BARS + s * 16;
        MBARRIER_WAIT_PARITY(fb, ph);
        uint32_t st = sb + OFF_TILES + s * STAGE_BYTES;
        uint32_t aB = st + (kgroup ? OFF_A1 : OFF_A0);
        uint32_t bB = st + OFF_B;

#pragma unroll
        for (int ks2 = 0; ks2 < 2; ks2++) {
            // A fragments: 8 x LDS.64 (fp32 pairs) -> 8 packed fp16x2 regs
            uint32_t a[2][4];
            float2 p;
            p = lds64(aB + rA0 +        cA0[ks2]); a[0][0] = packh2(p.y, p.x);
            p = lds64(aB + rA0 + 1024 + cA0[ks2]); a[0][1] = packh2(p.y, p.x);
            p = lds64(aB + rA0 +        cA1[ks2]); a[0][2] = packh2(p.y, p.x);
            p = lds64(aB + rA0 + 1024 + cA1[ks2]); a[0][3] = packh2(p.y, p.x);
            p = lds64(aB + rA0 + 2048 + cA0[ks2]); a[1][0] = packh2(p.y, p.x);
            p = lds64(aB + rA0 + 3072 + cA0[ks2]); a[1][1] = packh2(p.y, p.x);
            p = lds64(aB + rA0 + 2048 + cA1[ks2]); a[1][2] = packh2(p.y, p.x);
            p = lds64(aB + rA0 + 3072 + cA1[ks2]); a[1][3] = packh2(p.y, p.x);

#pragma unroll
            for (int nt = 0; nt < 8; nt++) {
                uint32_t b0 = lds32(bB + rB[nt] + cB0[ks2]);
                uint32_t b1 = lds32(bB + rB[nt] + cB1[ks2]);
                mma_f16(acc[0][nt], a[0][0], a[0][1], a[0][2], a[0][3], b0, b1);
                mma_f16(acc[1][nt], a[1][0], a[1][1], a[1][2], a[1][3], b0, b1);
            }
        }
        if (lid == 0) MBARRIER_ARRIVE(fb + 8);
        if (++s == STAGES) { s = 0; ph ^= 1; }
    }

    // -------- drain barrier: all compute warps done reading tile smem
    asm volatile("bar.sync 1, 256;" ::: "memory");

    // -------- reduction: kgroup 1 writes partials to smem, kgroup 0 adds
    float* part = reinterpret_cast<float*>(smem + OFF_TILES);
    if (kgroup == 1) {
#pragma unroll
        for (int mt = 0; mt < 2; mt++) {
            int r0 = cwid * 32 + mt * 16 + g;
#pragma unroll
            for (int nt = 0; nt < 8; nt++) {
                int col = nt * 8 + 2 * t;
                *reinterpret_cast<float2*>(part + (size_t)r0 * PART_STRIDE + col) =
                    make_float2(acc[mt][nt][0], acc[mt][nt][1]);
                *reinterpret_cast<float2*>(part + (size_t)(r0 + 8) * PART_STRIDE + col) =
                    make_float2(acc[mt][nt][2], acc[mt][nt][3]);
            }
        }
    }
    asm volatile("bar.sync 1, 256;" ::: "memory");

    if (kgroup == 0) {
        const float2* b2 = reinterpret_cast<const float2*>(bias);
        int row0 = m0 + cwid * 32 + g;
#pragma unroll
        for (int mt = 0; mt < 2; mt++) {
            int rloc = cwid * 32 + mt * 16 + g;
            int r = row0 + mt * 16;
#pragma unroll
            for (int nt = 0; nt < 8; nt++) {
                int col = nt * 8 + 2 * t;
                float2 bv = b2[col >> 1];
                float2 p0 = *reinterpret_cast<const float2*>(part + (size_t)rloc * PART_STRIDE + col);
                float2 p1 = *reinterpret_cast<const float2*>(part + (size_t)(rloc + 8) * PART_STRIDE + col);
                *reinterpret_cast<float2*>(out + (size_t)r * OUT_F + col) =
                    make_float2(acc[mt][nt][0] + p0.x + bv.x, acc[mt][nt][1] + p0.y + bv.y);
                *reinterpret_cast<float2*>(out + (size_t)(r + 8) * OUT_F + col) =
                    make_float2(acc[mt][nt][2] + p1.x + bv.x, acc[mt][nt][3] + p1.y + bv.y);
            }
        }
    }
}

// ---------------------------------------------------------------- host
typedef CUresult (*tmap_encode_fn)(
    CUtensorMap*, CUtensorMapDataType, cuuint32_t, void*,
    const cuuint64_t*, const cuuint64_t*, const cuuint32_t*, const cuuint32_t*,
    CUtensorMapInterleave, CUtensorMapSwizzle, CUtensorMapL2promotion,
    CUtensorMapFloatOOBfill);

extern "C" void kernel_launch(void* const* d_in, const int* in_sizes, int n_in,
                              void* d_out, int out_size) {
    const float* x    = (const float*)d_in[0];
    const float* adj  = (const float*)d_in[1];
    const float* w    = (const float*)d_in[2];
    const float* bias = (const float*)d_in[3];
    float* out = (float*)d_out;

    void* supT_ptr = nullptr;
    cudaGetSymbolAddress(&supT_ptr, g_supT);
    __half* supT = (__half*)supT_ptr;

    gcn_support_kernel<<<K_DIM / 64, 256>>>(x, w, supT);

    // Driver entry point via cudart (no -lcuda link dependency)
    tmap_encode_fn enc = nullptr;
    cudaDriverEntryPointQueryResult qr;
    cudaGetDriverEntryPointByVersion("cuTensorMapEncodeTiled", (void**)&enc, 12000,
                                     cudaEnableDefault, &qr);

    CUtensorMap madj{}, msup{};
    {
        cuuint64_t dims[2]    = {(cuuint64_t)K_DIM, (cuuint64_t)N_ROWS};
        cuuint64_t strides[1] = {(cuuint64_t)K_DIM * sizeof(float)};
        cuuint32_t box[2]     = {32, TILE_M};       // 128B x 128 rows, SW128
        cuuint32_t es[2]      = {1, 1};
        enc(&madj, CU_TENSOR_MAP_DATA_TYPE_FLOAT32, 2, (void*)adj,
            dims, strides, box, es,
            CU_TENSOR_MAP_INTERLEAVE_NONE, CU_TENSOR_MAP_SWIZZLE_128B,
            CU_TENSOR_MAP_L2_PROMOTION_L2_128B, CU_TENSOR_MAP_FLOAT_OOB_FILL_NONE);
    }
    {
        cuuint64_t dims[2]    = {(cuuint64_t)K_DIM, (cuuint64_t)OUT_F};
        cuuint64_t strides[1] = {(cuuint64_t)K_DIM * sizeof(__half)};
        cuuint32_t box[2]     = {64, OUT_F};        // 64 fp16 = 128B x 64 rows, SW128
        cuuint32_t es[2]      = {1, 1};
        enc(&msup, CU_TENSOR_MAP_DATA_TYPE_FLOAT16, 2, (void*)supT,
            dims, strides, box, es,
            CU_TENSOR_MAP_INTERLEAVE_NONE, CU_TENSOR_MAP_SWIZZLE_128B,
            CU_TENSOR_MAP_L2_PROMOTION_L2_128B, CU_TENSOR_MAP_FLOAT_OOB_FILL_NONE);
    }

    cudaFuncSetAttribute(gcn_gemm_kernel, cudaFuncAttributeMaxDynamicSharedMemorySize,
                         SMEM_BYTES);
    gcn_gemm_kernel<<<N_ROWS / TILE_M, 288, SMEM_BYTES>>>(madj, msup, out, bias);
}